// round 1
// baseline (speedup 1.0000x reference)
#include <cuda_runtime.h>
#include <cuda_bf16.h>

#define N_NODES 50000
#define E_EDGES 800000
#define DIM     128

// ---------------- scratch (static device allocations; no cudaMalloc) -------
__device__ float g_h[N_NODES * DIM];      // current features between layers
__device__ float g_hW[N_NODES * DIM];     // GEMM output per layer
__device__ float g_dinv[N_NODES];         // 1/sqrt(deg)
__device__ int   g_deg[N_NODES];          // in-degree incl. self loop
__device__ int   g_rowstart[N_NODES + 1]; // CSR offsets (in-edges, no self loops)
__device__ int   g_off[N_NODES];          // fill cursors
__device__ int   g_csr_src[E_EDGES];
__device__ float g_csr_norm[E_EDGES];

// ---------------- precompute kernels ---------------------------------------
__global__ void init_deg_kernel() {
    int i = blockIdx.x * blockDim.x + threadIdx.x;
    if (i < N_NODES) g_deg[i] = 1;            // self loop
}

__global__ void count_deg_kernel(const int* __restrict__ dst) {
    int e = blockIdx.x * blockDim.x + threadIdx.x;
    if (e < E_EDGES) atomicAdd(&g_deg[dst[e]], 1);
}

__global__ void dinv_kernel() {
    int i = blockIdx.x * blockDim.x + threadIdx.x;
    if (i < N_NODES) g_dinv[i] = rsqrtf((float)g_deg[i]);
}

// single-block exclusive scan of in-edge counts (deg-1) -> rowstart, off
__global__ void scan_kernel() {
    __shared__ int partial[1024];
    const int T = 1024;
    int t = threadIdx.x;
    const int chunk = (N_NODES + T - 1) / T;   // 49
    int start = t * chunk;
    int end   = start + chunk; if (end > N_NODES) end = N_NODES;
    int s = 0;
    for (int i = start; i < end; i++) s += g_deg[i] - 1;
    partial[t] = s;
    __syncthreads();
    if (t == 0) {
        int run = 0;
        for (int i = 0; i < T; i++) { int v = partial[i]; partial[i] = run; run += v; }
    }
    __syncthreads();
    int run = partial[t];
    for (int i = start; i < end; i++) {
        int c = g_deg[i] - 1;
        g_rowstart[i] = run;
        g_off[i] = run;
        run += c;
    }
    if (t == T - 1) g_rowstart[N_NODES] = run;   // == E_EDGES
}

__global__ void fill_csr_kernel(const int* __restrict__ src, const int* __restrict__ dst) {
    int e = blockIdx.x * blockDim.x + threadIdx.x;
    if (e >= E_EDGES) return;
    int s = src[e], d = dst[e];
    int pos = atomicAdd(&g_off[d], 1);
    g_csr_src[pos]  = s;
    g_csr_norm[pos] = g_dinv[s] * g_dinv[d];
}

// ---------------- SGEMM: C[M,128] = A[M,128] @ W[128,128] ------------------
// 128x128 block tile, BK=8 double-buffered, 8x8 register tile, 256 threads.
__global__ __launch_bounds__(256)
void sgemm128_kernel(const float* __restrict__ A, const float* __restrict__ W,
                     float* __restrict__ C, int M) {
    __shared__ float As[2][8][128];   // transposed: As[k][m]
    __shared__ float Bs[2][8][128];   // Bs[k][n]

    const int tid   = threadIdx.x;
    const int brow0 = blockIdx.x * 128;

    // global-load mapping
    const int a_r = tid >> 1;            // 0..127 row within tile
    const int a_c = (tid & 1) << 2;      // 0 or 4 (k offset)
    const int b_r = tid >> 5;            // 0..7  (k)
    const int b_c = (tid & 31) << 2;     // 0..124 (n)

    // compute mapping
    const int ty = tid >> 4;             // 0..15
    const int tx = tid & 15;             // 0..15
    const int m0 = ty << 3;
    const int n0 = tx << 3;

    float acc[8][8];
#pragma unroll
    for (int i = 0; i < 8; i++)
#pragma unroll
        for (int j = 0; j < 8; j++) acc[i][j] = 0.0f;

    const int gr = brow0 + a_r;

    // prologue: stage 0
    {
        float4 va = make_float4(0.f, 0.f, 0.f, 0.f);
        if (gr < M) va = *(const float4*)(A + (size_t)gr * DIM + a_c);
        float4 vb = *(const float4*)(W + b_r * DIM + b_c);
        As[0][a_c + 0][a_r] = va.x;
        As[0][a_c + 1][a_r] = va.y;
        As[0][a_c + 2][a_r] = va.z;
        As[0][a_c + 3][a_r] = va.w;
        *(float4*)&Bs[0][b_r][b_c] = vb;
    }
    __syncthreads();

#pragma unroll
    for (int kt = 0; kt < 16; kt++) {
        const int cur = kt & 1;
        float4 na = make_float4(0.f, 0.f, 0.f, 0.f), nb = make_float4(0.f, 0.f, 0.f, 0.f);
        const bool more = (kt + 1 < 16);
        if (more) {   // register-stage next tile (overlap LDG with FFMA)
            int k0 = (kt + 1) * 8;
            if (gr < M) na = *(const float4*)(A + (size_t)gr * DIM + k0 + a_c);
            nb = *(const float4*)(W + (k0 + b_r) * DIM + b_c);
        }
#pragma unroll
        for (int k = 0; k < 8; k++) {
            float a[8], b[8];
            *(float4*)(a)     = *(const float4*)&As[cur][k][m0];
            *(float4*)(a + 4) = *(const float4*)&As[cur][k][m0 + 4];
            *(float4*)(b)     = *(const float4*)&Bs[cur][k][n0];
            *(float4*)(b + 4) = *(const float4*)&Bs[cur][k][n0 + 4];
#pragma unroll
            for (int i = 0; i < 8; i++)
#pragma unroll
                for (int j = 0; j < 8; j++)
                    acc[i][j] = fmaf(a[i], b[j], acc[i][j]);
        }
        if (more) {
            const int nxt = cur ^ 1;
            As[nxt][a_c + 0][a_r] = na.x;
            As[nxt][a_c + 1][a_r] = na.y;
            As[nxt][a_c + 2][a_r] = na.z;
            As[nxt][a_c + 3][a_r] = na.w;
            *(float4*)&Bs[nxt][b_r][b_c] = nb;
        }
        __syncthreads();
    }

#pragma unroll
    for (int i = 0; i < 8; i++) {
        int grow = brow0 + m0 + i;
        if (grow < M) {
            *(float4*)(C + (size_t)grow * DIM + n0)     = make_float4(acc[i][0], acc[i][1], acc[i][2], acc[i][3]);
            *(float4*)(C + (size_t)grow * DIM + n0 + 4) = make_float4(acc[i][4], acc[i][5], acc[i][6], acc[i][7]);
        }
    }
}

// ---------------- aggregate: warp per node, pull over CSR ------------------
// out[n] = (relu?) ( bias + dinv[n]^2*hW[n] + sum_j norm_j * hW[src_j] ) (+resid)
__global__ __launch_bounds__(256)
void aggregate_kernel(const float* __restrict__ hW, const float* __restrict__ bias,
                      const float* __restrict__ resid, float* __restrict__ out,
                      int do_relu) {
    const int gw   = (blockIdx.x * blockDim.x + threadIdx.x) >> 5;
    const int lane = threadIdx.x & 31;
    if (gw >= N_NODES) return;

    const float4* hw4 = (const float4*)hW;

    float4 acc = ((const float4*)bias)[lane];
    {
        float dn = g_dinv[gw];
        float sw = dn * dn;
        float4 hv = hw4[(size_t)gw * 32 + lane];
        acc.x = fmaf(sw, hv.x, acc.x);
        acc.y = fmaf(sw, hv.y, acc.y);
        acc.z = fmaf(sw, hv.z, acc.z);
        acc.w = fmaf(sw, hv.w, acc.w);
    }

    int j  = g_rowstart[gw];
    const int je = g_rowstart[gw + 1];

    // unroll-2 for memory-level parallelism
    for (; j + 2 <= je; j += 2) {
        int   s0 = g_csr_src[j],     s1 = g_csr_src[j + 1];
        float w0 = g_csr_norm[j],    w1 = g_csr_norm[j + 1];
        float4 v0 = hw4[(size_t)s0 * 32 + lane];
        float4 v1 = hw4[(size_t)s1 * 32 + lane];
        acc.x = fmaf(w0, v0.x, acc.x);
        acc.y = fmaf(w0, v0.y, acc.y);
        acc.z = fmaf(w0, v0.z, acc.z);
        acc.w = fmaf(w0, v0.w, acc.w);
        acc.x = fmaf(w1, v1.x, acc.x);
        acc.y = fmaf(w1, v1.y, acc.y);
        acc.z = fmaf(w1, v1.z, acc.z);
        acc.w = fmaf(w1, v1.w, acc.w);
    }
    if (j < je) {
        int   s0 = g_csr_src[j];
        float w0 = g_csr_norm[j];
        float4 v0 = hw4[(size_t)s0 * 32 + lane];
        acc.x = fmaf(w0, v0.x, acc.x);
        acc.y = fmaf(w0, v0.y, acc.y);
        acc.z = fmaf(w0, v0.z, acc.z);
        acc.w = fmaf(w0, v0.w, acc.w);
    }

    if (do_relu) {
        acc.x = fmaxf(acc.x, 0.f);
        acc.y = fmaxf(acc.y, 0.f);
        acc.z = fmaxf(acc.z, 0.f);
        acc.w = fmaxf(acc.w, 0.f);
    }
    if (resid != nullptr) {
        float4 r = ((const float4*)resid)[(size_t)gw * 32 + lane];
        acc.x += r.x; acc.y += r.y; acc.z += r.z; acc.w += r.w;
    }
    ((float4*)out)[(size_t)gw * 32 + lane] = acc;
}

// ---------------- launch ----------------------------------------------------
extern "C" void kernel_launch(void* const* d_in, const int* in_sizes, int n_in,
                              void* d_out, int out_size) {
    const float* x   = (const float*)d_in[0];
    const int*   ei  = (const int*)d_in[1];
    const int*   src = ei;
    const int*   dst = ei + E_EDGES;
    const float* W0  = (const float*)d_in[2];
    const float* b0  = (const float*)d_in[3];
    const float* W1  = (const float*)d_in[4];
    const float* b1  = (const float*)d_in[5];
    const float* W2  = (const float*)d_in[6];
    const float* b2  = (const float*)d_in[7];
    float* out = (float*)d_out;

    float *hPtr = nullptr, *hWPtr = nullptr;
    cudaGetSymbolAddress((void**)&hPtr,  g_h);
    cudaGetSymbolAddress((void**)&hWPtr, g_hW);

    const int nblk  = (N_NODES + 255) / 256;            // 196
    const int eblk  = (E_EDGES + 255) / 256;            // 3125
    const int gblk  = (N_NODES + 127) / 128;            // 391
    const int ablk  = (N_NODES * 32 + 255) / 256;       // 6250

    // precompute: degree, dinv, CSR
    init_deg_kernel<<<nblk, 256>>>();
    count_deg_kernel<<<eblk, 256>>>(dst);
    dinv_kernel<<<nblk, 256>>>();
    scan_kernel<<<1, 1024>>>();
    fill_csr_kernel<<<eblk, 256>>>(src, dst);

    // layer 0: hW = x @ W0 ; h = relu(agg(hW) + b0)
    sgemm128_kernel<<<gblk, 256>>>(x, W0, hWPtr, N_NODES);
    aggregate_kernel<<<ablk, 256>>>(hWPtr, b0, nullptr, hPtr, 1);

    // layer 1
    sgemm128_kernel<<<gblk, 256>>>(hPtr, W1, hWPtr, N_NODES);
    aggregate_kernel<<<ablk, 256>>>(hWPtr, b1, nullptr, hPtr, 1);

    // layer 2: out = agg(hW) + b2 + x
    sgemm128_kernel<<<gblk, 256>>>(hPtr, W2, hWPtr, N_NODES);
    aggregate_kernel<<<ablk, 256>>>(hWPtr, b2, x, out, 0);
}

// round 2
// speedup vs baseline: 1.1909x; 1.1909x over previous
#include <cuda_runtime.h>
#include <cuda_bf16.h>

#define N_NODES 50000
#define E_EDGES 800000
#define DIM     128
#define SCAN_NB 196   // ceil(N_NODES/256)

// ---------------- scratch (static device allocations; no cudaMalloc) -------
__device__ float g_h[N_NODES * DIM];      // current features between layers
__device__ float g_hW[N_NODES * DIM];     // GEMM output per layer
__device__ float g_dinv[N_NODES];         // 1/sqrt(deg)
__device__ int   g_deg[N_NODES];          // in-edge count (no self loop)
__device__ int   g_rowstart[N_NODES + 1]; // CSR offsets (in-edges)
__device__ int   g_off[N_NODES];          // fill cursors
__device__ int   g_csr_src[E_EDGES];
__device__ float g_csr_norm[E_EDGES];
__device__ int   g_bsum[SCAN_NB];
__device__ int   g_boff[SCAN_NB];

// ---------------- precompute kernels ---------------------------------------
__global__ void init_deg_kernel() {
    int i = blockIdx.x * blockDim.x + threadIdx.x;
    if (i < N_NODES) g_deg[i] = 0;
}

__global__ void count_deg_kernel(const int* __restrict__ dst) {
    int e = blockIdx.x * blockDim.x + threadIdx.x;
    if (e < E_EDGES) atomicAdd(&g_deg[dst[e]], 1);
}

__global__ void dinv_kernel() {
    int i = blockIdx.x * blockDim.x + threadIdx.x;
    if (i < N_NODES) g_dinv[i] = rsqrtf((float)(g_deg[i] + 1));  // +1 self loop
}

// block-wide exclusive scan of v over 256 threads; returns exclusive prefix
__device__ __forceinline__ int block_exclusive_scan_256(int v, int tid) {
    __shared__ int wsum[8];
    const int lane = tid & 31, wid = tid >> 5;
    int inc = v;
#pragma unroll
    for (int d = 1; d < 32; d <<= 1) {
        int y = __shfl_up_sync(0xffffffffu, inc, d);
        if (lane >= d) inc += y;
    }
    if (lane == 31) wsum[wid] = inc;
    __syncthreads();
    if (tid == 0) {
        int run = 0;
#pragma unroll
        for (int w = 0; w < 8; w++) { int t = wsum[w]; wsum[w] = run; run += t; }
    }
    __syncthreads();
    return wsum[wid] + inc - v;
}

// stage 1: per-block sums of deg
__global__ __launch_bounds__(256) void scan_bsum_kernel() {
    __shared__ int wsum[8];
    const int tid = threadIdx.x;
    const int i = blockIdx.x * 256 + tid;
    int v = (i < N_NODES) ? g_deg[i] : 0;
    const int lane = tid & 31, wid = tid >> 5;
#pragma unroll
    for (int d = 16; d > 0; d >>= 1) v += __shfl_down_sync(0xffffffffu, v, d);
    if (lane == 0) wsum[wid] = v;
    __syncthreads();
    if (tid == 0) {
        int s = 0;
#pragma unroll
        for (int w = 0; w < 8; w++) s += wsum[w];
        g_bsum[blockIdx.x] = s;
    }
}

// stage 2: single block scans 196 block sums
__global__ __launch_bounds__(256) void scan_boff_kernel() {
    const int tid = threadIdx.x;
    int v = (tid < SCAN_NB) ? g_bsum[tid] : 0;
    int e = block_exclusive_scan_256(v, tid);
    if (tid < SCAN_NB) g_boff[tid] = e;
    if (tid == SCAN_NB - 1) g_rowstart[N_NODES] = e + v;   // total == E_EDGES
}

// stage 3: local exclusive scan + block offset -> rowstart, off
__global__ __launch_bounds__(256) void scan_write_kernel() {
    const int tid = threadIdx.x;
    const int i = blockIdx.x * 256 + tid;
    int v = (i < N_NODES) ? g_deg[i] : 0;
    int e = block_exclusive_scan_256(v, tid) + g_boff[blockIdx.x];
    if (i < N_NODES) { g_rowstart[i] = e; g_off[i] = e; }
}

__global__ void fill_csr_kernel(const int* __restrict__ src, const int* __restrict__ dst) {
    int e = blockIdx.x * blockDim.x + threadIdx.x;
    if (e >= E_EDGES) return;
    int s = src[e], d = dst[e];
    int pos = atomicAdd(&g_off[d], 1);
    g_csr_src[pos]  = s;
    g_csr_norm[pos] = g_dinv[s] * g_dinv[d];
}

// ---------------- SGEMM: C[M,128] = A[M,128] @ W[128,128] ------------------
// 128x128 block tile, BK=8 double-buffered, 8x8 register tile, 256 threads.
__global__ __launch_bounds__(256)
void sgemm128_kernel(const float* __restrict__ A, const float* __restrict__ W,
                     float* __restrict__ C, int M) {
    __shared__ float As[2][8][128];   // transposed: As[k][m]
    __shared__ float Bs[2][8][128];   // Bs[k][n]

    const int tid   = threadIdx.x;
    const int brow0 = blockIdx.x * 128;

    const int a_r = tid >> 1;            // 0..127 row within tile
    const int a_c = (tid & 1) << 2;      // 0 or 4 (k offset)
    const int b_r = tid >> 5;            // 0..7  (k)
    const int b_c = (tid & 31) << 2;     // 0..124 (n)

    const int ty = tid >> 4;             // 0..15
    const int tx = tid & 15;             // 0..15
    const int m0 = ty << 3;
    const int n0 = tx << 3;

    float acc[8][8];
#pragma unroll
    for (int i = 0; i < 8; i++)
#pragma unroll
        for (int j = 0; j < 8; j++) acc[i][j] = 0.0f;

    const int gr = brow0 + a_r;

    {
        float4 va = make_float4(0.f, 0.f, 0.f, 0.f);
        if (gr < M) va = *(const float4*)(A + (size_t)gr * DIM + a_c);
        float4 vb = *(const float4*)(W + b_r * DIM + b_c);
        As[0][a_c + 0][a_r] = va.x;
        As[0][a_c + 1][a_r] = va.y;
        As[0][a_c + 2][a_r] = va.z;
        As[0][a_c + 3][a_r] = va.w;
        *(float4*)&Bs[0][b_r][b_c] = vb;
    }
    __syncthreads();

#pragma unroll
    for (int kt = 0; kt < 16; kt++) {
        const int cur = kt & 1;
        float4 na = make_float4(0.f, 0.f, 0.f, 0.f), nb = make_float4(0.f, 0.f, 0.f, 0.f);
        const bool more = (kt + 1 < 16);
        if (more) {
            int k0 = (kt + 1) * 8;
            if (gr < M) na = *(const float4*)(A + (size_t)gr * DIM + k0 + a_c);
            nb = *(const float4*)(W + (k0 + b_r) * DIM + b_c);
        }
#pragma unroll
        for (int k = 0; k < 8; k++) {
            float a[8], b[8];
            *(float4*)(a)     = *(const float4*)&As[cur][k][m0];
            *(float4*)(a + 4) = *(const float4*)&As[cur][k][m0 + 4];
            *(float4*)(b)     = *(const float4*)&Bs[cur][k][n0];
            *(float4*)(b + 4) = *(const float4*)&Bs[cur][k][n0 + 4];
#pragma unroll
            for (int i = 0; i < 8; i++)
#pragma unroll
                for (int j = 0; j < 8; j++)
                    acc[i][j] = fmaf(a[i], b[j], acc[i][j]);
        }
        if (more) {
            const int nxt = cur ^ 1;
            As[nxt][a_c + 0][a_r] = na.x;
            As[nxt][a_c + 1][a_r] = na.y;
            As[nxt][a_c + 2][a_r] = na.z;
            As[nxt][a_c + 3][a_r] = na.w;
            *(float4*)&Bs[nxt][b_r][b_c] = nb;
        }
        __syncthreads();
    }

#pragma unroll
    for (int i = 0; i < 8; i++) {
        int grow = brow0 + m0 + i;
        if (grow < M) {
            *(float4*)(C + (size_t)grow * DIM + n0)     = make_float4(acc[i][0], acc[i][1], acc[i][2], acc[i][3]);
            *(float4*)(C + (size_t)grow * DIM + n0 + 4) = make_float4(acc[i][4], acc[i][5], acc[i][6], acc[i][7]);
        }
    }
}

// ---------------- aggregate: warp per node, pull over CSR ------------------
__global__ __launch_bounds__(256)
void aggregate_kernel(const float* __restrict__ hW, const float* __restrict__ bias,
                      const float* __restrict__ resid, float* __restrict__ out,
                      int do_relu) {
    const int gw   = (blockIdx.x * blockDim.x + threadIdx.x) >> 5;
    const int lane = threadIdx.x & 31;
    if (gw >= N_NODES) return;

    const float4* hw4 = (const float4*)hW;

    float4 acc = ((const float4*)bias)[lane];
    {
        float dn = g_dinv[gw];
        float sw = dn * dn;
        float4 hv = hw4[(size_t)gw * 32 + lane];
        acc.x = fmaf(sw, hv.x, acc.x);
        acc.y = fmaf(sw, hv.y, acc.y);
        acc.z = fmaf(sw, hv.z, acc.z);
        acc.w = fmaf(sw, hv.w, acc.w);
    }

    int j  = g_rowstart[gw];
    const int je = g_rowstart[gw + 1];

    for (; j + 2 <= je; j += 2) {
        int   s0 = g_csr_src[j],     s1 = g_csr_src[j + 1];
        float w0 = g_csr_norm[j],    w1 = g_csr_norm[j + 1];
        float4 v0 = hw4[(size_t)s0 * 32 + lane];
        float4 v1 = hw4[(size_t)s1 * 32 + lane];
        acc.x = fmaf(w0, v0.x, acc.x);
        acc.y = fmaf(w0, v0.y, acc.y);
        acc.z = fmaf(w0, v0.z, acc.z);
        acc.w = fmaf(w0, v0.w, acc.w);
        acc.x = fmaf(w1, v1.x, acc.x);
        acc.y = fmaf(w1, v1.y, acc.y);
        acc.z = fmaf(w1, v1.z, acc.z);
        acc.w = fmaf(w1, v1.w, acc.w);
    }
    if (j < je) {
        int   s0 = g_csr_src[j];
        float w0 = g_csr_norm[j];
        float4 v0 = hw4[(size_t)s0 * 32 + lane];
        acc.x = fmaf(w0, v0.x, acc.x);
        acc.y = fmaf(w0, v0.y, acc.y);
        acc.z = fmaf(w0, v0.z, acc.z);
        acc.w = fmaf(w0, v0.w, acc.w);
    }

    if (do_relu) {
        acc.x = fmaxf(acc.x, 0.f);
        acc.y = fmaxf(acc.y, 0.f);
        acc.z = fmaxf(acc.z, 0.f);
        acc.w = fmaxf(acc.w, 0.f);
    }
    if (resid != nullptr) {
        float4 r = ((const float4*)resid)[(size_t)gw * 32 + lane];
        acc.x += r.x; acc.y += r.y; acc.z += r.z; acc.w += r.w;
    }
    ((float4*)out)[(size_t)gw * 32 + lane] = acc;
}

// ---------------- launch ----------------------------------------------------
extern "C" void kernel_launch(void* const* d_in, const int* in_sizes, int n_in,
                              void* d_out, int out_size) {
    const float* x   = (const float*)d_in[0];
    const int*   ei  = (const int*)d_in[1];
    const int*   src = ei;
    const int*   dst = ei + E_EDGES;
    const float* W0  = (const float*)d_in[2];
    const float* b0  = (const float*)d_in[3];
    const float* W1  = (const float*)d_in[4];
    const float* b1  = (const float*)d_in[5];
    const float* W2  = (const float*)d_in[6];
    const float* b2  = (const float*)d_in[7];
    float* out = (float*)d_out;

    float *hPtr = nullptr, *hWPtr = nullptr;
    cudaGetSymbolAddress((void**)&hPtr,  g_h);
    cudaGetSymbolAddress((void**)&hWPtr, g_hW);

    const int nblk  = (N_NODES + 255) / 256;            // 196
    const int eblk  = (E_EDGES + 255) / 256;            // 3125
    const int gblk  = (N_NODES + 127) / 128;            // 391
    const int ablk  = (N_NODES * 32 + 255) / 256;       // 6250

    // precompute: degree, dinv, CSR (hierarchical scan)
    init_deg_kernel<<<nblk, 256>>>();
    count_deg_kernel<<<eblk, 256>>>(dst);
    dinv_kernel<<<nblk, 256>>>();
    scan_bsum_kernel<<<SCAN_NB, 256>>>();
    scan_boff_kernel<<<1, 256>>>();
    scan_write_kernel<<<SCAN_NB, 256>>>();
    fill_csr_kernel<<<eblk, 256>>>(src, dst);

    // layer 0
    sgemm128_kernel<<<gblk, 256>>>(x, W0, hWPtr, N_NODES);
    aggregate_kernel<<<ablk, 256>>>(hWPtr, b0, nullptr, hPtr, 1);

    // layer 1
    sgemm128_kernel<<<gblk, 256>>>(hPtr, W1, hWPtr, N_NODES);
    aggregate_kernel<<<ablk, 256>>>(hWPtr, b1, nullptr, hPtr, 1);

    // layer 2: out = agg(hW) + b2 + x
    sgemm128_kernel<<<gblk, 256>>>(hPtr, W2, hWPtr, N_NODES);
    aggregate_kernel<<<ablk, 256>>>(hWPtr, b2, x, out, 0);
}

// round 3
// speedup vs baseline: 1.3406x; 1.1257x over previous
#include <cuda_runtime.h>
#include <cuda_fp16.h>

#define N_NODES 50000
#define E_EDGES 800000
#define DIM     128
#define SCAN_NB 196   // ceil(N_NODES/256)

// ---------------- scratch (static device allocations; no cudaMalloc) -------
__device__ float  g_h[N_NODES * DIM];      // current features between layers (fp32)
__device__ __half g_hWh[N_NODES * DIM];    // GEMM output per layer (fp16 intermediate)
__device__ float  g_dinv[N_NODES];         // 1/sqrt(deg)
__device__ int    g_deg[N_NODES];          // in-edge count (no self loop)
__device__ int    g_rowstart[N_NODES + 1]; // CSR offsets (in-edges)
__device__ int    g_off[N_NODES];          // fill cursors
__device__ int    g_csr_src[E_EDGES];
__device__ float  g_csr_norm[E_EDGES];
__device__ int    g_bsum[SCAN_NB];
__device__ int    g_boff[SCAN_NB];

// ---------------- precompute kernels ---------------------------------------
__global__ void init_deg_kernel() {
    int i = blockIdx.x * blockDim.x + threadIdx.x;
    if (i < N_NODES) g_deg[i] = 0;
}

__global__ void count_deg_kernel(const int* __restrict__ dst) {
    int e = blockIdx.x * blockDim.x + threadIdx.x;
    if (e < E_EDGES) atomicAdd(&g_deg[dst[e]], 1);
}

__global__ void dinv_kernel() {
    int i = blockIdx.x * blockDim.x + threadIdx.x;
    if (i < N_NODES) g_dinv[i] = rsqrtf((float)(g_deg[i] + 1));  // +1 self loop
}

// block-wide exclusive scan of v over 256 threads; returns exclusive prefix
__device__ __forceinline__ int block_exclusive_scan_256(int v, int tid) {
    __shared__ int wsum[8];
    const int lane = tid & 31, wid = tid >> 5;
    int inc = v;
#pragma unroll
    for (int d = 1; d < 32; d <<= 1) {
        int y = __shfl_up_sync(0xffffffffu, inc, d);
        if (lane >= d) inc += y;
    }
    if (lane == 31) wsum[wid] = inc;
    __syncthreads();
    if (tid == 0) {
        int run = 0;
#pragma unroll
        for (int w = 0; w < 8; w++) { int t = wsum[w]; wsum[w] = run; run += t; }
    }
    __syncthreads();
    return wsum[wid] + inc - v;
}

// stage 1: per-block sums of deg
__global__ __launch_bounds__(256) void scan_bsum_kernel() {
    __shared__ int wsum[8];
    const int tid = threadIdx.x;
    const int i = blockIdx.x * 256 + tid;
    int v = (i < N_NODES) ? g_deg[i] : 0;
    const int lane = tid & 31, wid = tid >> 5;
#pragma unroll
    for (int d = 16; d > 0; d >>= 1) v += __shfl_down_sync(0xffffffffu, v, d);
    if (lane == 0) wsum[wid] = v;
    __syncthreads();
    if (tid == 0) {
        int s = 0;
#pragma unroll
        for (int w = 0; w < 8; w++) s += wsum[w];
        g_bsum[blockIdx.x] = s;
    }
}

// stage 2: single block scans 196 block sums
__global__ __launch_bounds__(256) void scan_boff_kernel() {
    const int tid = threadIdx.x;
    int v = (tid < SCAN_NB) ? g_bsum[tid] : 0;
    int e = block_exclusive_scan_256(v, tid);
    if (tid < SCAN_NB) g_boff[tid] = e;
    if (tid == SCAN_NB - 1) g_rowstart[N_NODES] = e + v;   // total == E_EDGES
}

// stage 3: local exclusive scan + block offset -> rowstart, off
__global__ __launch_bounds__(256) void scan_write_kernel() {
    const int tid = threadIdx.x;
    const int i = blockIdx.x * 256 + tid;
    int v = (i < N_NODES) ? g_deg[i] : 0;
    int e = block_exclusive_scan_256(v, tid) + g_boff[blockIdx.x];
    if (i < N_NODES) { g_rowstart[i] = e; g_off[i] = e; }
}

__global__ void fill_csr_kernel(const int* __restrict__ src, const int* __restrict__ dst) {
    int e = blockIdx.x * blockDim.x + threadIdx.x;
    if (e >= E_EDGES) return;
    int s = src[e], d = dst[e];
    int pos = atomicAdd(&g_off[d], 1);
    g_csr_src[pos]  = s;
    g_csr_norm[pos] = g_dinv[s] * g_dinv[d];
}

// ---------------- SGEMM: C[M,128](fp16) = A[M,128](fp32) @ W[128,128] ------
// 128x128 block tile, BK=8 double-buffered, 8x8 register tile, 256 threads.
__global__ __launch_bounds__(256)
void sgemm128_kernel(const float* __restrict__ A, const float* __restrict__ W,
                     __half* __restrict__ C, int M) {
    __shared__ float As[2][8][128];   // transposed: As[k][m]
    __shared__ float Bs[2][8][128];   // Bs[k][n]

    const int tid   = threadIdx.x;
    const int brow0 = blockIdx.x * 128;

    const int a_r = tid >> 1;            // 0..127 row within tile
    const int a_c = (tid & 1) << 2;      // 0 or 4 (k offset)
    const int b_r = tid >> 5;            // 0..7  (k)
    const int b_c = (tid & 31) << 2;     // 0..124 (n)

    const int ty = tid >> 4;             // 0..15
    const int tx = tid & 15;             // 0..15
    const int m0 = ty << 3;
    const int n0 = tx << 3;

    float acc[8][8];
#pragma unroll
    for (int i = 0; i < 8; i++)
#pragma unroll
        for (int j = 0; j < 8; j++) acc[i][j] = 0.0f;

    const int gr = brow0 + a_r;

    {
        float4 va = make_float4(0.f, 0.f, 0.f, 0.f);
        if (gr < M) va = *(const float4*)(A + (size_t)gr * DIM + a_c);
        float4 vb = *(const float4*)(W + b_r * DIM + b_c);
        As[0][a_c + 0][a_r] = va.x;
        As[0][a_c + 1][a_r] = va.y;
        As[0][a_c + 2][a_r] = va.z;
        As[0][a_c + 3][a_r] = va.w;
        *(float4*)&Bs[0][b_r][b_c] = vb;
    }
    __syncthreads();

#pragma unroll
    for (int kt = 0; kt < 16; kt++) {
        const int cur = kt & 1;
        float4 na = make_float4(0.f, 0.f, 0.f, 0.f), nb = make_float4(0.f, 0.f, 0.f, 0.f);
        const bool more = (kt + 1 < 16);
        if (more) {
            int k0 = (kt + 1) * 8;
            if (gr < M) na = *(const float4*)(A + (size_t)gr * DIM + k0 + a_c);
            nb = *(const float4*)(W + (k0 + b_r) * DIM + b_c);
        }
#pragma unroll
        for (int k = 0; k < 8; k++) {
            float a[8], b[8];
            *(float4*)(a)     = *(const float4*)&As[cur][k][m0];
            *(float4*)(a + 4) = *(const float4*)&As[cur][k][m0 + 4];
            *(float4*)(b)     = *(const float4*)&Bs[cur][k][n0];
            *(float4*)(b + 4) = *(const float4*)&Bs[cur][k][n0 + 4];
#pragma unroll
            for (int i = 0; i < 8; i++)
#pragma unroll
                for (int j = 0; j < 8; j++)
                    acc[i][j] = fmaf(a[i], b[j], acc[i][j]);
        }
        if (more) {
            const int nxt = cur ^ 1;
            As[nxt][a_c + 0][a_r] = na.x;
            As[nxt][a_c + 1][a_r] = na.y;
            As[nxt][a_c + 2][a_r] = na.z;
            As[nxt][a_c + 3][a_r] = na.w;
            *(float4*)&Bs[nxt][b_r][b_c] = nb;
        }
        __syncthreads();
    }

    // epilogue: convert to fp16, one 16B store per row-part (8 halves)
#pragma unroll
    for (int i = 0; i < 8; i++) {
        int grow = brow0 + m0 + i;
        if (grow < M) {
            __half2 hp[4];
            hp[0] = __floats2half2_rn(acc[i][0], acc[i][1]);
            hp[1] = __floats2half2_rn(acc[i][2], acc[i][3]);
            hp[2] = __floats2half2_rn(acc[i][4], acc[i][5]);
            hp[3] = __floats2half2_rn(acc[i][6], acc[i][7]);
            *(uint4*)(C + (size_t)grow * DIM + n0) = *(uint4*)hp;
        }
    }
}

// ---------------- aggregate: warp per node, pull over CSR (fp16 gather) ----
// out[n] = (relu?) ( bias + dinv[n]^2*hW[n] + sum_j norm_j * hW[src_j] ) (+resid)
__global__ __launch_bounds__(256)
void aggregate_kernel(const __half2* __restrict__ hw2, const float* __restrict__ bias,
                      const float* __restrict__ resid, float* __restrict__ out,
                      int do_relu) {
    const int gw   = (blockIdx.x * blockDim.x + threadIdx.x) >> 5;
    const int lane = threadIdx.x & 31;
    if (gw >= N_NODES) return;

    // lane covers 4 columns: [lane*4, lane*4+4). hw2 index = node*64 + lane*2
    const int l2 = lane * 2;

    float4 acc = ((const float4*)bias)[lane];
    {
        float dn = g_dinv[gw];
        float sw = dn * dn;
        __half2 p0 = hw2[(size_t)gw * 64 + l2];
        __half2 p1 = hw2[(size_t)gw * 64 + l2 + 1];
        float2 f0 = __half22float2(p0), f1 = __half22float2(p1);
        acc.x = fmaf(sw, f0.x, acc.x);
        acc.y = fmaf(sw, f0.y, acc.y);
        acc.z = fmaf(sw, f1.x, acc.z);
        acc.w = fmaf(sw, f1.y, acc.w);
    }

    int j  = g_rowstart[gw];
    const int je = g_rowstart[gw + 1];

#define AGG_ONE(idx)                                                     \
    {                                                                    \
        int   _s = g_csr_src[(idx)];                                     \
        float _w = g_csr_norm[(idx)];                                    \
        __half2 _p0 = hw2[(size_t)_s * 64 + l2];                         \
        __half2 _p1 = hw2[(size_t)_s * 64 + l2 + 1];                     \
        float2 _f0 = __half22float2(_p0), _f1 = __half22float2(_p1);     \
        acc.x = fmaf(_w, _f0.x, acc.x);                                  \
        acc.y = fmaf(_w, _f0.y, acc.y);                                  \
        acc.z = fmaf(_w, _f1.x, acc.z);                                  \
        acc.w = fmaf(_w, _f1.y, acc.w);                                  \
    }

    for (; j + 4 <= je; j += 4) {
        AGG_ONE(j); AGG_ONE(j + 1); AGG_ONE(j + 2); AGG_ONE(j + 3);
    }
    for (; j < je; j++) AGG_ONE(j);
#undef AGG_ONE

    if (do_relu) {
        acc.x = fmaxf(acc.x, 0.f);
        acc.y = fmaxf(acc.y, 0.f);
        acc.z = fmaxf(acc.z, 0.f);
        acc.w = fmaxf(acc.w, 0.f);
    }
    if (resid != nullptr) {
        float4 r = ((const float4*)resid)[(size_t)gw * 32 + lane];
        acc.x += r.x; acc.y += r.y; acc.z += r.z; acc.w += r.w;
    }
    ((float4*)out)[(size_t)gw * 32 + lane] = acc;
}

// ---------------- launch ----------------------------------------------------
extern "C" void kernel_launch(void* const* d_in, const int* in_sizes, int n_in,
                              void* d_out, int out_size) {
    const float* x   = (const float*)d_in[0];
    const int*   ei  = (const int*)d_in[1];
    const int*   src = ei;
    const int*   dst = ei + E_EDGES;
    const float* W0  = (const float*)d_in[2];
    const float* b0  = (const float*)d_in[3];
    const float* W1  = (const float*)d_in[4];
    const float* b1  = (const float*)d_in[5];
    const float* W2  = (const float*)d_in[6];
    const float* b2  = (const float*)d_in[7];
    float* out = (float*)d_out;

    float  *hPtr  = nullptr;
    __half *hWPtr = nullptr;
    cudaGetSymbolAddress((void**)&hPtr,  g_h);
    cudaGetSymbolAddress((void**)&hWPtr, g_hWh);
    const __half2* hw2 = (const __half2*)hWPtr;

    const int nblk  = (N_NODES + 255) / 256;            // 196
    const int eblk  = (E_EDGES + 255) / 256;            // 3125
    const int gblk  = (N_NODES + 127) / 128;            // 391
    const int ablk  = (N_NODES * 32 + 255) / 256;       // 6250

    // precompute: degree, dinv, CSR (hierarchical scan)
    init_deg_kernel<<<nblk, 256>>>();
    count_deg_kernel<<<eblk, 256>>>(dst);
    dinv_kernel<<<nblk, 256>>>();
    scan_bsum_kernel<<<SCAN_NB, 256>>>();
    scan_boff_kernel<<<1, 256>>>();
    scan_write_kernel<<<SCAN_NB, 256>>>();
    fill_csr_kernel<<<eblk, 256>>>(src, dst);

    // layer 0
    sgemm128_kernel<<<gblk, 256>>>(x, W0, hWPtr, N_NODES);
    aggregate_kernel<<<ablk, 256>>>(hw2, b0, nullptr, hPtr, 1);

    // layer 1
    sgemm128_kernel<<<gblk, 256>>>(hPtr, W1, hWPtr, N_NODES);
    aggregate_kernel<<<ablk, 256>>>(hw2, b1, nullptr, hPtr, 1);

    // layer 2: out = agg(hW) + b2 + x
    sgemm128_kernel<<<gblk, 256>>>(hPtr, W2, hWPtr, N_NODES);
    aggregate_kernel<<<ablk, 256>>>(hw2, b2, x, out, 0);
}

// round 7
// speedup vs baseline: 2.5679x; 1.9155x over previous
#include <cuda_runtime.h>
#include <cuda_fp16.h>
#include <cstdint>

#define N_NODES 50000
#define E_EDGES 800000
#define DIM     128
#define SCAN_NB 196   // ceil(N_NODES/256)
#define AS      136   // smem tile stride in halves (128 + 8 pad)

// ---------------- scratch (static device allocations; no cudaMalloc) -------
__device__ __half g_hh[N_NODES * DIM];     // features between layers (fp16)
__device__ __half g_hWh[N_NODES * DIM];    // GEMM output per layer (fp16)
__device__ __half g_Wh[3 * DIM * DIM];     // fp16 weights
__device__ float  g_dinv[N_NODES];         // 1/sqrt(deg)
__device__ int    g_deg[N_NODES];          // in-edge count (no self loop)
__device__ int    g_rowstart[N_NODES + 1]; // CSR offsets (in-edges)
__device__ int    g_off[N_NODES];          // fill cursors
__device__ int    g_csr_src[E_EDGES];
__device__ float  g_csr_norm[E_EDGES];
__device__ int    g_bsum[SCAN_NB];
__device__ int    g_boff[SCAN_NB];

// ---------------- fp32 -> fp16 convert -------------------------------------
__global__ void f2h_kernel(const float* __restrict__ in, __half* __restrict__ out, int n4) {
    int i = blockIdx.x * blockDim.x + threadIdx.x;
    if (i >= n4) return;
    float4 v = ((const float4*)in)[i];
    __half2 h0 = __floats2half2_rn(v.x, v.y);
    __half2 h1 = __floats2half2_rn(v.z, v.w);
    uint2 p;
    p.x = *(unsigned*)&h0;
    p.y = *(unsigned*)&h1;
    ((uint2*)out)[i] = p;
}

// ---------------- precompute kernels ---------------------------------------
__global__ void init_deg_kernel() {
    int i = blockIdx.x * blockDim.x + threadIdx.x;
    if (i < N_NODES) g_deg[i] = 0;
}

__global__ void count_deg_kernel(const int* __restrict__ dst) {
    int e = blockIdx.x * blockDim.x + threadIdx.x;
    if (e < E_EDGES) atomicAdd(&g_deg[dst[e]], 1);
}

__global__ void dinv_kernel() {
    int i = blockIdx.x * blockDim.x + threadIdx.x;
    if (i < N_NODES) g_dinv[i] = rsqrtf((float)(g_deg[i] + 1));  // +1 self loop
}

__device__ __forceinline__ int block_exclusive_scan_256(int v, int tid) {
    __shared__ int wsum[8];
    const int lane = tid & 31, wid = tid >> 5;
    int inc = v;
#pragma unroll
    for (int d = 1; d < 32; d <<= 1) {
        int y = __shfl_up_sync(0xffffffffu, inc, d);
        if (lane >= d) inc += y;
    }
    if (lane == 31) wsum[wid] = inc;
    __syncthreads();
    if (tid == 0) {
        int run = 0;
#pragma unroll
        for (int w = 0; w < 8; w++) { int t = wsum[w]; wsum[w] = run; run += t; }
    }
    __syncthreads();
    return wsum[wid] + inc - v;
}

__global__ __launch_bounds__(256) void scan_bsum_kernel() {
    __shared__ int wsum[8];
    const int tid = threadIdx.x;
    const int i = blockIdx.x * 256 + tid;
    int v = (i < N_NODES) ? g_deg[i] : 0;
    const int lane = tid & 31, wid = tid >> 5;
#pragma unroll
    for (int d = 16; d > 0; d >>= 1) v += __shfl_down_sync(0xffffffffu, v, d);
    if (lane == 0) wsum[wid] = v;
    __syncthreads();
    if (tid == 0) {
        int s = 0;
#pragma unroll
        for (int w = 0; w < 8; w++) s += wsum[w];
        g_bsum[blockIdx.x] = s;
    }
}

__global__ __launch_bounds__(256) void scan_boff_kernel() {
    const int tid = threadIdx.x;
    int v = (tid < SCAN_NB) ? g_bsum[tid] : 0;
    int e = block_exclusive_scan_256(v, tid);
    if (tid < SCAN_NB) g_boff[tid] = e;
    if (tid == SCAN_NB - 1) g_rowstart[N_NODES] = e + v;
}

__global__ __launch_bounds__(256) void scan_write_kernel() {
    const int tid = threadIdx.x;
    const int i = blockIdx.x * 256 + tid;
    int v = (i < N_NODES) ? g_deg[i] : 0;
    int e = block_exclusive_scan_256(v, tid) + g_boff[blockIdx.x];
    if (i < N_NODES) { g_rowstart[i] = e; g_off[i] = e; }
}

__global__ void fill_csr_kernel(const int* __restrict__ src, const int* __restrict__ dst) {
    int e = blockIdx.x * blockDim.x + threadIdx.x;
    if (e >= E_EDGES) return;
    int s = src[e], d = dst[e];
    int pos = atomicAdd(&g_off[d], 1);
    g_csr_src[pos]  = s;
    g_csr_norm[pos] = g_dinv[s] * g_dinv[d];
}

// ---------------- HGEMM via mma.sync (tensor cores) ------------------------
__device__ __forceinline__ void ldsm_x4(unsigned r[4], unsigned addr) {
    asm volatile("ldmatrix.sync.aligned.m8n8.x4.shared.b16 {%0,%1,%2,%3}, [%4];"
                 : "=r"(r[0]), "=r"(r[1]), "=r"(r[2]), "=r"(r[3]) : "r"(addr));
}
__device__ __forceinline__ void ldsm_x4_trans(unsigned r[4], unsigned addr) {
    asm volatile("ldmatrix.sync.aligned.m8n8.x4.trans.shared.b16 {%0,%1,%2,%3}, [%4];"
                 : "=r"(r[0]), "=r"(r[1]), "=r"(r[2]), "=r"(r[3]) : "r"(addr));
}
__device__ __forceinline__ void mma_16816(float c[4], const unsigned a[4], const unsigned b[2]) {
    asm volatile("mma.sync.aligned.m16n8k16.row.col.f32.f16.f16.f32 "
                 "{%0,%1,%2,%3}, {%4,%5,%6,%7}, {%8,%9}, {%0,%1,%2,%3};"
                 : "+f"(c[0]), "+f"(c[1]), "+f"(c[2]), "+f"(c[3])
                 : "r"(a[0]), "r"(a[1]), "r"(a[2]), "r"(a[3]), "r"(b[0]), "r"(b[1]));
}

// C[M,128](fp16) = A[M,128](fp16) @ W[128,128](fp16), fp32 accumulate.
// 128x128 tile per block, 8 warps: 4 along M (32 rows), 2 along N (64 cols).
__global__ __launch_bounds__(256)
void hgemm128_kernel(const __half* __restrict__ A, const __half* __restrict__ W,
                     __half* __restrict__ C, int M) {
    extern __shared__ __align__(16) __half sm[];
    __half* Asm = sm;                  // [128][AS]
    __half* Bsm = sm + 128 * AS;       // [128][AS]

    const int tid   = threadIdx.x;
    const int brow0 = blockIdx.x * 128;

    // stage full tiles (K=128 one-shot)
#pragma unroll
    for (int i = 0; i < 8; i++) {
        int idx = tid + i * 256;       // 0..2047
        int r   = idx >> 4;            // row 0..127
        int c8  = idx & 15;            // uint4 index within row
        int gr  = brow0 + r;
        uint4 v = make_uint4(0u, 0u, 0u, 0u);
        if (gr < M) v = ((const uint4*)(A + (size_t)gr * DIM))[c8];
        *(uint4*)&Asm[r * AS + c8 * 8] = v;
        uint4 w = ((const uint4*)(W + (size_t)r * DIM))[c8];
        *(uint4*)&Bsm[r * AS + c8 * 8] = w;
    }
    __syncthreads();

    const int warp = tid >> 5, lane = tid & 31;
    const int m0 = (warp & 3) * 32;    // warp M origin
    const int n0 = (warp >> 2) * 64;   // warp N origin
    const int l15 = lane & 15;
    const int lhi = lane >> 4;

    float c[2][8][4];
#pragma unroll
    for (int t = 0; t < 2; t++)
#pragma unroll
        for (int n = 0; n < 8; n++)
#pragma unroll
            for (int q = 0; q < 4; q++) c[t][n][q] = 0.0f;

#pragma unroll
    for (int kk = 0; kk < 8; kk++) {
        const int k0 = kk * 16;
        unsigned a[2][4];
#pragma unroll
        for (int t = 0; t < 2; t++) {
            unsigned ad = (unsigned)__cvta_generic_to_shared(
                &Asm[(m0 + t * 16 + l15) * AS + k0 + lhi * 8]);
            ldsm_x4(a[t], ad);
        }
        unsigned b[8][2];
#pragma unroll
        for (int j = 0; j < 4; j++) {
            unsigned ad = (unsigned)__cvta_generic_to_shared(
                &Bsm[(k0 + l15) * AS + n0 + j * 16 + lhi * 8]);
            unsigned r[4];
            ldsm_x4_trans(r, ad);
            b[2 * j][0]     = r[0]; b[2 * j][1]     = r[1];
            b[2 * j + 1][0] = r[2]; b[2 * j + 1][1] = r[3];
        }
#pragma unroll
        for (int t = 0; t < 2; t++)
#pragma unroll
            for (int n = 0; n < 8; n++)
                mma_16816(c[t][n], a[t], b[n]);
    }

    // epilogue: fp32 acc -> fp16 stores
    const int rq = lane >> 2;          // 0..7
    const int cq = (lane & 3) * 2;     // 0,2,4,6
#pragma unroll
    for (int t = 0; t < 2; t++) {
#pragma unroll
        for (int n = 0; n < 8; n++) {
            int row = brow0 + m0 + t * 16 + rq;
            int col = n0 + n * 8 + cq;
            if (row < M) {
                __half2 h = __floats2half2_rn(c[t][n][0], c[t][n][1]);
                *(__half2*)&C[(size_t)row * DIM + col] = h;
            }
            if (row + 8 < M) {
                __half2 h = __floats2half2_rn(c[t][n][2], c[t][n][3]);
                *(__half2*)&C[(size_t)(row + 8) * DIM + col] = h;
            }
        }
    }
}

// ---------------- aggregate: warp per node, pull over CSR (fp16 gather) ----
#define AGG_BODY()                                                           \
    const int gw   = (blockIdx.x * blockDim.x + threadIdx.x) >> 5;           \
    const int lane = threadIdx.x & 31;                                       \
    if (gw >= N_NODES) return;                                               \
    const int l2 = lane * 2;                                                 \
    float4 acc = ((const float4*)bias)[lane];                                \
    {                                                                        \
        float dn = g_dinv[gw];                                               \
        float sw = dn * dn;                                                  \
        __half2 p0 = hw2[(size_t)gw * 64 + l2];                              \
        __half2 p1 = hw2[(size_t)gw * 64 + l2 + 1];                          \
        float2 f0 = __half22float2(p0), f1 = __half22float2(p1);             \
        acc.x = fmaf(sw, f0.x, acc.x);                                       \
        acc.y = fmaf(sw, f0.y, acc.y);                                       \
        acc.z = fmaf(sw, f1.x, acc.z);                                       \
        acc.w = fmaf(sw, f1.y, acc.w);                                       \
    }                                                                        \
    int j  = g_rowstart[gw];                                                 \
    const int je = g_rowstart[gw + 1];                                       \
    for (; j + 4 <= je; j += 4) {                                            \
        AGG_ONE(j); AGG_ONE(j + 1); AGG_ONE(j + 2); AGG_ONE(j + 3);          \
    }                                                                        \
    for (; j < je; j++) AGG_ONE(j);

#define AGG_ONE(idx)                                                     \
    {                                                                    \
        int   _s = g_csr_src[(idx)];                                     \
        float _w = g_csr_norm[(idx)];                                    \
        __half2 _p0 = hw2[(size_t)_s * 64 + l2];                         \
        __half2 _p1 = hw2[(size_t)_s * 64 + l2 + 1];                     \
        float2 _f0 = __half22float2(_p0), _f1 = __half22float2(_p1);     \
        acc.x = fmaf(_w, _f0.x, acc.x);                                  \
        acc.y = fmaf(_w, _f0.y, acc.y);                                  \
        acc.z = fmaf(_w, _f1.x, acc.z);                                  \
        acc.w = fmaf(_w, _f1.y, acc.w);                                  \
    }

// hidden layers: relu, fp16 output
__global__ __launch_bounds__(256)
void aggregate_h_kernel(const __half2* __restrict__ hw2, const float* __restrict__ bias,
                        __half* __restrict__ out) {
    AGG_BODY();
    acc.x = fmaxf(acc.x, 0.f);
    acc.y = fmaxf(acc.y, 0.f);
    acc.z = fmaxf(acc.z, 0.f);
    acc.w = fmaxf(acc.w, 0.f);
    __half2 o0 = __floats2half2_rn(acc.x, acc.y);
    __half2 o1 = __floats2half2_rn(acc.z, acc.w);
    uint2 p;
    p.x = *(unsigned*)&o0;
    p.y = *(unsigned*)&o1;
    *(uint2*)&out[(size_t)gw * DIM + lane * 4] = p;
}

// final layer: residual, fp32 output
__global__ __launch_bounds__(256)
void aggregate_f_kernel(const __half2* __restrict__ hw2, const float* __restrict__ bias,
                        const float* __restrict__ resid, float* __restrict__ out) {
    AGG_BODY();
    float4 r = ((const float4*)resid)[(size_t)gw * 32 + lane];
    acc.x += r.x; acc.y += r.y; acc.z += r.z; acc.w += r.w;
    ((float4*)out)[(size_t)gw * 32 + lane] = acc;
}
#undef AGG_ONE
#undef AGG_BODY

// ---------------- launch ----------------------------------------------------
extern "C" void kernel_launch(void* const* d_in, const int* in_sizes, int n_in,
                              void* d_out, int out_size) {
    const float* x   = (const float*)d_in[0];
    const int*   ei  = (const int*)d_in[1];
    const int*   src = ei;
    const int*   dst = ei + E_EDGES;
    const float* W0  = (const float*)d_in[2];
    const float* b0  = (const float*)d_in[3];
    const float* W1  = (const float*)d_in[4];
    const float* b1  = (const float*)d_in[5];
    const float* W2  = (const float*)d_in[6];
    const float* b2  = (const float*)d_in[7];
    float* out = (float*)d_out;

    __half *hPtr = nullptr, *hWPtr = nullptr, *WhPtr = nullptr;
    cudaGetSymbolAddress((void**)&hPtr,  g_hh);
    cudaGetSymbolAddress((void**)&hWPtr, g_hWh);
    cudaGetSymbolAddress((void**)&WhPtr, g_Wh);
    const __half2* hw2 = (const __half2*)hWPtr;

    const int smem = 2 * 128 * AS * (int)sizeof(__half);   // 69632
    static int attr_done = 0;
    if (!attr_done) {
        cudaFuncSetAttribute(hgemm128_kernel,
                             cudaFuncAttributeMaxDynamicSharedMemorySize, smem);
        attr_done = 1;
    }

    const int nblk  = (N_NODES + 255) / 256;            // 196
    const int eblk  = (E_EDGES + 255) / 256;            // 3125
    const int gblk  = (N_NODES + 127) / 128;            // 391
    const int ablk  = (N_NODES * 32 + 255) / 256;       // 6250
    const int xblk  = (N_NODES * DIM / 4 + 255) / 256;  // 6250
    const int wblk  = (DIM * DIM / 4 + 255) / 256;      // 16

    // converts
    f2h_kernel<<<xblk, 256>>>(x,  hPtr,  N_NODES * DIM / 4);
    f2h_kernel<<<wblk, 256>>>(W0, WhPtr,              DIM * DIM / 4);
    f2h_kernel<<<wblk, 256>>>(W1, WhPtr + DIM * DIM,  DIM * DIM / 4);
    f2h_kernel<<<wblk, 256>>>(W2, WhPtr + 2 * DIM * DIM, DIM * DIM / 4);

    // precompute: degree, dinv, CSR (hierarchical scan)
    init_deg_kernel<<<nblk, 256>>>();
    count_deg_kernel<<<eblk, 256>>>(dst);
    dinv_kernel<<<nblk, 256>>>();
    scan_bsum_kernel<<<SCAN_NB, 256>>>();
    scan_boff_kernel<<<1, 256>>>();
    scan_write_kernel<<<SCAN_NB, 256>>>();
    fill_csr_kernel<<<eblk, 256>>>(src, dst);

    // layer 0
    hgemm128_kernel<<<gblk, 256, smem>>>(hPtr, WhPtr, hWPtr, N_NODES);
    aggregate_h_kernel<<<ablk, 256>>>(hw2, b0, hPtr);

    // layer 1
    hgemm128_kernel<<<gblk, 256, smem>>>(hPtr, WhPtr + DIM * DIM, hWPtr, N_NODES);
    aggregate_h_kernel<<<ablk, 256>>>(hw2, b1, hPtr);

    // layer 2: out = agg(hW) + b2 + x
    hgemm128_kernel<<<gblk, 256, smem>>>(hPtr, WhPtr + 2 * DIM * DIM, hWPtr, N_NODES);
    aggregate_f_kernel<<<ablk, 256>>>(hw2, b2, x, out);
}

// round 11
// speedup vs baseline: 2.9901x; 1.1644x over previous
#include <cuda_runtime.h>
#include <cuda_fp16.h>
#include <cstdint>

#define N_NODES 50000
#define E_EDGES 800000
#define DIM     128
#define SCAN_NB 196   // ceil(N_NODES/256)
#define AS      136   // smem tile stride in halves (128 + 8 pad)
#define XQ      (N_NODES * DIM / 4)   // float4 count of x
#define WQ      (DIM * DIM / 4)       // float4 count of one W

// ---------------- scratch (static device allocations; no cudaMalloc) -------
__device__ __half g_hh[N_NODES * DIM];     // features between layers (fp16)
__device__ __half g_hWh[N_NODES * DIM];    // GEMM output per layer (fp16)
__device__ __half g_Wh[3 * DIM * DIM];     // fp16 weights
__device__ float  g_dinv[N_NODES];         // 1/sqrt(deg)
__device__ int    g_deg[N_NODES];          // in-edge count (no self loop)
__device__ int    g_rowstart[N_NODES + 1]; // CSR offsets (in-edges)
__device__ int    g_off[N_NODES];          // fill cursors
__device__ int2   g_csr[E_EDGES];          // (src, norm bits) packed
__device__ int    g_bsum[SCAN_NB];
__device__ int    g_boff[SCAN_NB];

// ---------------- merged fp32 -> fp16 convert (x + 3 weights) --------------
__device__ __forceinline__ void cvt4(const float* __restrict__ in, __half* __restrict__ out, int q) {
    float4 v = ((const float4*)in)[q];
    __half2 h0 = __floats2half2_rn(v.x, v.y);
    __half2 h1 = __floats2half2_rn(v.z, v.w);
    uint2 p;
    p.x = *(unsigned*)&h0;
    p.y = *(unsigned*)&h1;
    ((uint2*)out)[q] = p;
}

__global__ void convert_all_kernel(const float* __restrict__ x,
                                   const float* __restrict__ W0,
                                   const float* __restrict__ W1,
                                   const float* __restrict__ W2) {
    int i = blockIdx.x * blockDim.x + threadIdx.x;
    if (i < XQ) { cvt4(x, g_hh, i); return; }
    int q = i - XQ;
    if (q < WQ)            { cvt4(W0, g_Wh,               q);          return; }
    if (q < 2 * WQ)        { cvt4(W1, g_Wh + DIM * DIM,   q - WQ);     return; }
    if (q < 3 * WQ)        { cvt4(W2, g_Wh + 2 * DIM * DIM, q - 2 * WQ); }
}

// ---------------- precompute kernels ---------------------------------------
__global__ void init_deg_kernel() {
    int i = blockIdx.x * blockDim.x + threadIdx.x;
    if (i < N_NODES) g_deg[i] = 0;
}

__global__ void count_deg_kernel(const int* __restrict__ dst) {
    int e = blockIdx.x * blockDim.x + threadIdx.x;
    if (e < E_EDGES) atomicAdd(&g_deg[dst[e]], 1);
}

__device__ __forceinline__ int block_exclusive_scan_256(int v, int tid) {
    __shared__ int wsum[8];
    const int lane = tid & 31, wid = tid >> 5;
    int inc = v;
#pragma unroll
    for (int d = 1; d < 32; d <<= 1) {
        int y = __shfl_up_sync(0xffffffffu, inc, d);
        if (lane >= d) inc += y;
    }
    if (lane == 31) wsum[wid] = inc;
    __syncthreads();
    if (tid == 0) {
        int run = 0;
#pragma unroll
        for (int w = 0; w < 8; w++) { int t = wsum[w]; wsum[w] = run; run += t; }
    }
    __syncthreads();
    return wsum[wid] + inc - v;
}

// stage 1: per-block sums of deg; also computes dinv (fused)
__global__ __launch_bounds__(256) void scan_bsum_kernel() {
    __shared__ int wsum[8];
    const int tid = threadIdx.x;
    const int i = blockIdx.x * 256 + tid;
    int v = 0;
    if (i < N_NODES) {
        v = g_deg[i];
        g_dinv[i] = rsqrtf((float)(v + 1));   // +1 self loop
    }
    const int lane = tid & 31, wid = tid >> 5;
#pragma unroll
    for (int d = 16; d > 0; d >>= 1) v += __shfl_down_sync(0xffffffffu, v, d);
    if (lane == 0) wsum[wid] = v;
    __syncthreads();
    if (tid == 0) {
        int s = 0;
#pragma unroll
        for (int w = 0; w < 8; w++) s += wsum[w];
        g_bsum[blockIdx.x] = s;
    }
}

__global__ __launch_bounds__(256) void scan_boff_kernel() {
    const int tid = threadIdx.x;
    int v = (tid < SCAN_NB) ? g_bsum[tid] : 0;
    int e = block_exclusive_scan_256(v, tid);
    if (tid < SCAN_NB) g_boff[tid] = e;
    if (tid == SCAN_NB - 1) g_rowstart[N_NODES] = e + v;
}

__global__ __launch_bounds__(256) void scan_write_kernel() {
    const int tid = threadIdx.x;
    const int i = blockIdx.x * 256 + tid;
    int v = (i < N_NODES) ? g_deg[i] : 0;
    int e = block_exclusive_scan_256(v, tid) + g_boff[blockIdx.x];
    if (i < N_NODES) { g_rowstart[i] = e; g_off[i] = e; }
}

__global__ void fill_csr_kernel(const int* __restrict__ src, const int* __restrict__ dst) {
    int e = blockIdx.x * blockDim.x + threadIdx.x;
    if (e >= E_EDGES) return;
    int s = src[e], d = dst[e];
    int pos = atomicAdd(&g_off[d], 1);
    float nm = g_dinv[s] * g_dinv[d];
    g_csr[pos] = make_int2(s, __float_as_int(nm));
}

// ---------------- HGEMM via mma.sync (tensor cores) ------------------------
__device__ __forceinline__ void ldsm_x4(unsigned r[4], unsigned addr) {
    asm volatile("ldmatrix.sync.aligned.m8n8.x4.shared.b16 {%0,%1,%2,%3}, [%4];"
                 : "=r"(r[0]), "=r"(r[1]), "=r"(r[2]), "=r"(r[3]) : "r"(addr));
}
__device__ __forceinline__ void ldsm_x4_trans(unsigned r[4], unsigned addr) {
    asm volatile("ldmatrix.sync.aligned.m8n8.x4.trans.shared.b16 {%0,%1,%2,%3}, [%4];"
                 : "=r"(r[0]), "=r"(r[1]), "=r"(r[2]), "=r"(r[3]) : "r"(addr));
}
__device__ __forceinline__ void mma_16816(float c[4], const unsigned a[4], const unsigned b[2]) {
    asm volatile("mma.sync.aligned.m16n8k16.row.col.f32.f16.f16.f32 "
                 "{%0,%1,%2,%3}, {%4,%5,%6,%7}, {%8,%9}, {%0,%1,%2,%3};"
                 : "+f"(c[0]), "+f"(c[1]), "+f"(c[2]), "+f"(c[3])
                 : "r"(a[0]), "r"(a[1]), "r"(a[2]), "r"(a[3]), "r"(b[0]), "r"(b[1]));
}

// C[M,128](fp16) = A[M,128](fp16) @ W[128,128](fp16), fp32 accumulate.
__global__ __launch_bounds__(256)
void hgemm128_kernel(const __half* __restrict__ A, const __half* __restrict__ W,
                     __half* __restrict__ C, int M) {
    extern __shared__ __align__(16) __half sm[];
    __half* Asm = sm;                  // [128][AS]
    __half* Bsm = sm + 128 * AS;       // [128][AS]

    const int tid   = threadIdx.x;
    const int brow0 = blockIdx.x * 128;

#pragma unroll
    for (int i = 0; i < 8; i++) {
        int idx = tid + i * 256;
        int r   = idx >> 4;
        int c8  = idx & 15;
        int gr  = brow0 + r;
        uint4 v = make_uint4(0u, 0u, 0u, 0u);
        if (gr < M) v = ((const uint4*)(A + (size_t)gr * DIM))[c8];
        *(uint4*)&Asm[r * AS + c8 * 8] = v;
        uint4 w = ((const uint4*)(W + (size_t)r * DIM))[c8];
        *(uint4*)&Bsm[r * AS + c8 * 8] = w;
    }
    __syncthreads();

    const int warp = tid >> 5, lane = tid & 31;
    const int m0 = (warp & 3) * 32;
    const int n0 = (warp >> 2) * 64;
    const int l15 = lane & 15;
    const int lhi = lane >> 4;

    float c[2][8][4];
#pragma unroll
    for (int t = 0; t < 2; t++)
#pragma unroll
        for (int n = 0; n < 8; n++)
#pragma unroll
            for (int q = 0; q < 4; q++) c[t][n][q] = 0.0f;

#pragma unroll
    for (int kk = 0; kk < 8; kk++) {
        const int k0 = kk * 16;
        unsigned a[2][4];
#pragma unroll
        for (int t = 0; t < 2; t++) {
            unsigned ad = (unsigned)__cvta_generic_to_shared(
                &Asm[(m0 + t * 16 + l15) * AS + k0 + lhi * 8]);
            ldsm_x4(a[t], ad);
        }
        unsigned b[8][2];
#pragma unroll
        for (int j = 0; j < 4; j++) {
            unsigned ad = (unsigned)__cvta_generic_to_shared(
                &Bsm[(k0 + l15) * AS + n0 + j * 16 + lhi * 8]);
            unsigned r[4];
            ldsm_x4_trans(r, ad);
            b[2 * j][0]     = r[0]; b[2 * j][1]     = r[1];
            b[2 * j + 1][0] = r[2]; b[2 * j + 1][1] = r[3];
        }
#pragma unroll
        for (int t = 0; t < 2; t++)
#pragma unroll
            for (int n = 0; n < 8; n++)
                mma_16816(c[t][n], a[t], b[n]);
    }

    const int rq = lane >> 2;
    const int cq = (lane & 3) * 2;
#pragma unroll
    for (int t = 0; t < 2; t++) {
#pragma unroll
        for (int n = 0; n < 8; n++) {
            int row = brow0 + m0 + t * 16 + rq;
            int col = n0 + n * 8 + cq;
            if (row < M) {
                __half2 h = __floats2half2_rn(c[t][n][0], c[t][n][1]);
                *(__half2*)&C[(size_t)row * DIM + col] = h;
            }
            if (row + 8 < M) {
                __half2 h = __floats2half2_rn(c[t][n][2], c[t][n][3]);
                *(__half2*)&C[(size_t)(row + 8) * DIM + col] = h;
            }
        }
    }
}

// ---------------- aggregate: warp per node, pull over CSR (fp16 gather) ----
// each lane handles 4 columns; one 8B gather + one 8B packed meta load per edge
#define AGG_BODY()                                                           \
    const int gw   = (blockIdx.x * blockDim.x + threadIdx.x) >> 5;           \
    const int lane = threadIdx.x & 31;                                       \
    if (gw >= N_NODES) return;                                               \
    float4 acc = ((const float4*)bias)[lane];                                \
    {                                                                        \
        float dn = g_dinv[gw];                                               \
        float sw = dn * dn;                                                  \
        uint2 pv = hw2[(size_t)gw * 32 + lane];                              \
        __half2 p0 = *(__half2*)&pv.x, p1 = *(__half2*)&pv.y;                \
        float2 f0 = __half22float2(p0), f1 = __half22float2(p1);             \
        acc.x = fmaf(sw, f0.x, acc.x);                                       \
        acc.y = fmaf(sw, f0.y, acc.y);                                       \
        acc.z = fmaf(sw, f1.x, acc.z);                                       \
        acc.w = fmaf(sw, f1.y, acc.w);                                       \
    }                                                                        \
    int j  = g_rowstart[gw];                                                 \
    const int je = g_rowstart[gw + 1];                                       \
    for (; j + 4 <= je; j += 4) {                                            \
        AGG_ONE(j); AGG_ONE(j + 1); AGG_ONE(j + 2); AGG_ONE(j + 3);          \
    }                                                                        \
    for (; j < je; j++) AGG_ONE(j);

#define AGG_ONE(idx)                                                     \
    {                                                                    \
        int2  _e = g_csr[(idx)];                                         \
        float _w = __int_as_float(_e.y);                                 \
        uint2 _pv = hw2[(size_t)_e.x * 32 + lane];                       \
        __half2 _p0 = *(__half2*)&_pv.x, _p1 = *(__half2*)&_pv.y;        \
        float2 _f0 = __half22float2(_p0), _f1 = __half22float2(_p1);     \
        acc.x = fmaf(_w, _f0.x, acc.x);                                  \
        acc.y = fmaf(_w, _f0.y, acc.y);                                  \
        acc.z = fmaf(_w, _f1.x, acc.z);                                  \
        acc.w = fmaf(_w, _f1.y, acc.w);                                  \
    }

// hidden layers: relu, fp16 output
__global__ __launch_bounds__(256)
void aggregate_h_kernel(const uint2* __restrict__ hw2, const float* __restrict__ bias,
                        __half* __restrict__ out) {
    AGG_BODY();
    acc.x = fmaxf(acc.x, 0.f);
    acc.y = fmaxf(acc.y, 0.f);
    acc.z = fmaxf(acc.z, 0.f);
    acc.w = fmaxf(acc.w, 0.f);
    __half2 o0 = __floats2half2_rn(acc.x, acc.y);
    __half2 o1 = __floats2half2_rn(acc.z, acc.w);
    uint2 p;
    p.x = *(unsigned*)&o0;
    p.y = *(unsigned*)&o1;
    *(uint2*)&out[(size_t)gw * DIM + lane * 4] = p;
}

// final layer: residual, fp32 output
__global__ __launch_bounds__(256)
void aggregate_f_kernel(const uint2* __restrict__ hw2, const float* __restrict__ bias,
                        const float* __restrict__ resid, float* __restrict__ out) {
    AGG_BODY();
    float4 r = ((const float4*)resid)[(size_t)gw * 32 + lane];
    acc.x += r.x; acc.y += r.y; acc.z += r.z; acc.w += r.w;
    ((float4*)out)[(size_t)gw * 32 + lane] = acc;
}
#undef AGG_ONE
#undef AGG_BODY

// ---------------- launch ----------------------------------------------------
extern "C" void kernel_launch(void* const* d_in, const int* in_sizes, int n_in,
                              void* d_out, int out_size) {
    const float* x   = (const float*)d_in[0];
    const int*   ei  = (const int*)d_in[1];
    const int*   src = ei;
    const int*   dst = ei + E_EDGES;
    const float* W0  = (const float*)d_in[2];
    const float* b0  = (const float*)d_in[3];
    const float* W1  = (const float*)d_in[4];
    const float* b1  = (const float*)d_in[5];
    const float* W2  = (const float*)d_in[6];
    const float* b2  = (const float*)d_in[7];
    float* out = (float*)d_out;

    __half *hPtr = nullptr, *hWPtr = nullptr, *WhPtr = nullptr;
    cudaGetSymbolAddress((void**)&hPtr,  g_hh);
    cudaGetSymbolAddress((void**)&hWPtr, g_hWh);
    cudaGetSymbolAddress((void**)&WhPtr, g_Wh);
    const uint2* hw2 = (const uint2*)hWPtr;

    const int smem = 2 * 128 * AS * (int)sizeof(__half);   // 69632
    static int once = 0;
    static cudaStream_t s1;
    static cudaEvent_t evFork, evJoin;
    if (!once) {
        cudaFuncSetAttribute(hgemm128_kernel,
                             cudaFuncAttributeMaxDynamicSharedMemorySize, smem);
        cudaStreamCreateWithFlags(&s1, cudaStreamNonBlocking);
        cudaEventCreateWithFlags(&evFork, cudaEventDisableTiming);
        cudaEventCreateWithFlags(&evJoin, cudaEventDisableTiming);
        once = 1;
    }

    const int nblk  = (N_NODES + 255) / 256;                 // 196
    const int eblk  = (E_EDGES + 255) / 256;                 // 3125
    const int gblk  = (N_NODES + 127) / 128;                 // 391
    const int ablk  = (N_NODES * 32 + 255) / 256;            // 6250
    const int cblk  = (XQ + 3 * WQ + 255) / 256;             // 6298

    // ---- fork: branch A (side stream s1): converts + GEMM0 ----------------
    cudaEventRecord(evFork, 0);
    cudaStreamWaitEvent(s1, evFork, 0);
    convert_all_kernel<<<cblk, 256, 0, s1>>>(x, W0, W1, W2);
    hgemm128_kernel<<<gblk, 256, smem, s1>>>(hPtr, WhPtr, hWPtr, N_NODES);
    cudaEventRecord(evJoin, s1);

    // ---- branch B (main stream): degree, dinv, CSR -------------------------
    init_deg_kernel<<<nblk, 256>>>();
    count_deg_kernel<<<eblk, 256>>>(dst);
    scan_bsum_kernel<<<SCAN_NB, 256>>>();     // also writes dinv
    scan_boff_kernel<<<1, 256>>>();
    scan_write_kernel<<<SCAN_NB, 256>>>();
    fill_csr_kernel<<<eblk, 256>>>(src, dst);

    // ---- join --------------------------------------------------------------
    cudaStreamWaitEvent(0, evJoin, 0);

    // layer 0 aggregate
    aggregate_h_kernel<<<ablk, 256>>>(hw2, b0, hPtr);

    // layer 1
    hgemm128_kernel<<<gblk, 256, smem>>>(hPtr, WhPtr + DIM * DIM, hWPtr, N_NODES);
    aggregate_h_kernel<<<ablk, 256>>>(hw2, b1, hPtr);

    // layer 2: out = agg(hW) + b2 + x
    hgemm128_kernel<<<gblk, 256, smem>>>(hPtr, WhPtr + 2 * DIM * DIM, hWPtr, N_NODES);
    aggregate_f_kernel<<<ablk, 256>>>(hw2, b2, x, out);
}

// round 13
// speedup vs baseline: 3.0649x; 1.0250x over previous
#include <cuda_runtime.h>
#include <cuda_fp16.h>
#include <cstdint>

#define N_NODES 50000
#define E_EDGES 800000
#define DIM     128
#define SCAN_NB 196   // ceil(N_NODES/256)
#define AS      136   // smem tile stride in halves (128 + 8 pad)
#define XQ      (N_NODES * DIM / 4)   // float4 count of x
#define WQ      (DIM * DIM / 4)       // float4 count of one W

// ---------------- scratch (static device allocations; no cudaMalloc) -------
__device__ __half g_hh[N_NODES * DIM];     // features between layers (fp16)
__device__ __half g_hWh[N_NODES * DIM];    // dinv-scaled GEMM output (fp16)
__device__ __half g_Wh[3 * DIM * DIM];     // fp16 weights
__device__ float  g_dinv[N_NODES];         // 1/sqrt(deg)
__device__ int    g_deg[N_NODES];          // in-edge count (no self loop)
__device__ int    g_rowstart[N_NODES + 1]; // CSR offsets (in-edges)
__device__ int    g_off[N_NODES];          // fill cursors
__device__ int    g_csr_src[E_EDGES];      // src only (norm folded out)
__device__ int    g_bsum[SCAN_NB];
__device__ int    g_boff[SCAN_NB];

// ---------------- merged fp32 -> fp16 convert (x + 3 weights) --------------
__device__ __forceinline__ void cvt4(const float* __restrict__ in, __half* __restrict__ out, int q) {
    float4 v = ((const float4*)in)[q];
    __half2 h0 = __floats2half2_rn(v.x, v.y);
    __half2 h1 = __floats2half2_rn(v.z, v.w);
    uint2 p;
    p.x = *(unsigned*)&h0;
    p.y = *(unsigned*)&h1;
    ((uint2*)out)[q] = p;
}

__global__ void convert_all_kernel(const float* __restrict__ x,
                                   const float* __restrict__ W0,
                                   const float* __restrict__ W1,
                                   const float* __restrict__ W2) {
    int i = blockIdx.x * blockDim.x + threadIdx.x;
    if (i < XQ) { cvt4(x, g_hh, i); return; }
    int q = i - XQ;
    if (q < WQ)            { cvt4(W0, g_Wh,               q);          return; }
    if (q < 2 * WQ)        { cvt4(W1, g_Wh + DIM * DIM,   q - WQ);     return; }
    if (q < 3 * WQ)        { cvt4(W2, g_Wh + 2 * DIM * DIM, q - 2 * WQ); }
}

// ---------------- precompute kernels ---------------------------------------
// 4 edges per thread via int4
__global__ void count_deg_kernel(const int* __restrict__ dst) {
    int i = blockIdx.x * blockDim.x + threadIdx.x;
    if (i >= E_EDGES / 4) return;
    int4 d = ((const int4*)dst)[i];
    atomicAdd(&g_deg[d.x], 1);
    atomicAdd(&g_deg[d.y], 1);
    atomicAdd(&g_deg[d.z], 1);
    atomicAdd(&g_deg[d.w], 1);
}

__device__ __forceinline__ int block_exclusive_scan_256(int v, int tid) {
    __shared__ int wsum[8];
    const int lane = tid & 31, wid = tid >> 5;
    int inc = v;
#pragma unroll
    for (int d = 1; d < 32; d <<= 1) {
        int y = __shfl_up_sync(0xffffffffu, inc, d);
        if (lane >= d) inc += y;
    }
    if (lane == 31) wsum[wid] = inc;
    __syncthreads();
    if (tid == 0) {
        int run = 0;
#pragma unroll
        for (int w = 0; w < 8; w++) { int t = wsum[w]; wsum[w] = run; run += t; }
    }
    __syncthreads();
    return wsum[wid] + inc - v;
}

// stage 1: per-block sums of deg; also computes dinv (fused)
__global__ __launch_bounds__(256) void scan_bsum_kernel() {
    __shared__ int wsum[8];
    const int tid = threadIdx.x;
    const int i = blockIdx.x * 256 + tid;
    int v = 0;
    if (i < N_NODES) {
        v = g_deg[i];
        g_dinv[i] = rsqrtf((float)(v + 1));   // +1 self loop
    }
    const int lane = tid & 31, wid = tid >> 5;
#pragma unroll
    for (int d = 16; d > 0; d >>= 1) v += __shfl_down_sync(0xffffffffu, v, d);
    if (lane == 0) wsum[wid] = v;
    __syncthreads();
    if (tid == 0) {
        int s = 0;
#pragma unroll
        for (int w = 0; w < 8; w++) s += wsum[w];
        g_bsum[blockIdx.x] = s;
    }
}

__global__ __launch_bounds__(256) void scan_boff_kernel() {
    const int tid = threadIdx.x;
    int v = (tid < SCAN_NB) ? g_bsum[tid] : 0;
    int e = block_exclusive_scan_256(v, tid);
    if (tid < SCAN_NB) g_boff[tid] = e;
    if (tid == SCAN_NB - 1) g_rowstart[N_NODES] = e + v;
}

__global__ __launch_bounds__(256) void scan_write_kernel() {
    const int tid = threadIdx.x;
    const int i = blockIdx.x * 256 + tid;
    int v = (i < N_NODES) ? g_deg[i] : 0;
    int e = block_exclusive_scan_256(v, tid) + g_boff[blockIdx.x];
    if (i < N_NODES) { g_rowstart[i] = e; g_off[i] = e; }
}

// 4 edges per thread; store src only
__global__ void fill_csr_kernel(const int* __restrict__ src, const int* __restrict__ dst) {
    int i = blockIdx.x * blockDim.x + threadIdx.x;
    if (i >= E_EDGES / 4) return;
    int4 s = ((const int4*)src)[i];
    int4 d = ((const int4*)dst)[i];
    g_csr_src[atomicAdd(&g_off[d.x], 1)] = s.x;
    g_csr_src[atomicAdd(&g_off[d.y], 1)] = s.y;
    g_csr_src[atomicAdd(&g_off[d.z], 1)] = s.z;
    g_csr_src[atomicAdd(&g_off[d.w], 1)] = s.w;
}

// ---------------- HGEMM via mma.sync (tensor cores) ------------------------
__device__ __forceinline__ void ldsm_x4(unsigned r[4], unsigned addr) {
    asm volatile("ldmatrix.sync.aligned.m8n8.x4.shared.b16 {%0,%1,%2,%3}, [%4];"
                 : "=r"(r[0]), "=r"(r[1]), "=r"(r[2]), "=r"(r[3]) : "r"(addr));
}
__device__ __forceinline__ void ldsm_x4_trans(unsigned r[4], unsigned addr) {
    asm volatile("ldmatrix.sync.aligned.m8n8.x4.trans.shared.b16 {%0,%1,%2,%3}, [%4];"
                 : "=r"(r[0]), "=r"(r[1]), "=r"(r[2]), "=r"(r[3]) : "r"(addr));
}
__device__ __forceinline__ void mma_16816(float c[4], const unsigned a[4], const unsigned b[2]) {
    asm volatile("mma.sync.aligned.m16n8k16.row.col.f32.f16.f16.f32 "
                 "{%0,%1,%2,%3}, {%4,%5,%6,%7}, {%8,%9}, {%0,%1,%2,%3};"
                 : "+f"(c[0]), "+f"(c[1]), "+f"(c[2]), "+f"(c[3])
                 : "r"(a[0]), "r"(a[1]), "r"(a[2]), "r"(a[3]), "r"(b[0]), "r"(b[1]));
}

// C[M,128](fp16) = dinv[row] * (A[M,128](fp16) @ W[128,128](fp16)), fp32 acc.
__global__ __launch_bounds__(256)
void hgemm128_kernel(const __half* __restrict__ A, const __half* __restrict__ W,
                     __half* __restrict__ C, int M) {
    extern __shared__ __align__(16) __half sm[];
    __half* Asm = sm;                  // [128][AS]
    __half* Bsm = sm + 128 * AS;       // [128][AS]

    const int tid   = threadIdx.x;
    const int brow0 = blockIdx.x * 128;

#pragma unroll
    for (int i = 0; i < 8; i++) {
        int idx = tid + i * 256;
        int r   = idx >> 4;
        int c8  = idx & 15;
        int gr  = brow0 + r;
        uint4 v = make_uint4(0u, 0u, 0u, 0u);
        if (gr < M) v = ((const uint4*)(A + (size_t)gr * DIM))[c8];
        *(uint4*)&Asm[r * AS + c8 * 8] = v;
        uint4 w = ((const uint4*)(W + (size_t)r * DIM))[c8];
        *(uint4*)&Bsm[r * AS + c8 * 8] = w;
    }
    __syncthreads();

    const int warp = tid >> 5, lane = tid & 31;
    const int m0 = (warp & 3) * 32;
    const int n0 = (warp >> 2) * 64;
    const int l15 = lane & 15;
    const int lhi = lane >> 4;

    float c[2][8][4];
#pragma unroll
    for (int t = 0; t < 2; t++)
#pragma unroll
        for (int n = 0; n < 8; n++)
#pragma unroll
            for (int q = 0; q < 4; q++) c[t][n][q] = 0.0f;

#pragma unroll
    for (int kk = 0; kk < 8; kk++) {
        const int k0 = kk * 16;
        unsigned a[2][4];
#pragma unroll
        for (int t = 0; t < 2; t++) {
            unsigned ad = (unsigned)__cvta_generic_to_shared(
                &Asm[(m0 + t * 16 + l15) * AS + k0 + lhi * 8]);
            ldsm_x4(a[t], ad);
        }
        unsigned b[8][2];
#pragma unroll
        for (int j = 0; j < 4; j++) {
            unsigned ad = (unsigned)__cvta_generic_to_shared(
                &Bsm[(k0 + l15) * AS + n0 + j * 16 + lhi * 8]);
            unsigned r[4];
            ldsm_x4_trans(r, ad);
            b[2 * j][0]     = r[0]; b[2 * j][1]     = r[1];
            b[2 * j + 1][0] = r[2]; b[2 * j + 1][1] = r[3];
        }
#pragma unroll
        for (int t = 0; t < 2; t++)
#pragma unroll
            for (int n = 0; n < 8; n++)
                mma_16816(c[t][n], a[t], b[n]);
    }

    // epilogue: scale rows by dinv, convert to fp16
    const int rq = lane >> 2;
    const int cq = (lane & 3) * 2;
#pragma unroll
    for (int t = 0; t < 2; t++) {
        int row0 = brow0 + m0 + t * 16 + rq;
        int row1 = row0 + 8;
        float d0 = (row0 < M) ? g_dinv[row0] : 0.f;
        float d1 = (row1 < M) ? g_dinv[row1] : 0.f;
#pragma unroll
        for (int n = 0; n < 8; n++) {
            int col = n0 + n * 8 + cq;
            if (row0 < M) {
                __half2 h = __floats2half2_rn(d0 * c[t][n][0], d0 * c[t][n][1]);
                *(__half2*)&C[(size_t)row0 * DIM + col] = h;
            }
            if (row1 < M) {
                __half2 h = __floats2half2_rn(d1 * c[t][n][2], d1 * c[t][n][3]);
                *(__half2*)&C[(size_t)row1 * DIM + col] = h;
            }
        }
    }
}

// ---------------- aggregate: warp per node, unweighted pull over CSR -------
// acc = hW'[gw] + sum_j hW'[src_j];  result = dinv[gw]*acc + bias (+resid)
#define AGG_BODY()                                                           \
    const int gw   = (blockIdx.x * blockDim.x + threadIdx.x) >> 5;           \
    const int lane = threadIdx.x & 31;                                       \
    if (gw >= N_NODES) return;                                               \
    float4 acc;                                                              \
    {                                                                        \
        uint2 pv = hw2[(size_t)gw * 32 + lane];                              \
        __half2 p0 = *(__half2*)&pv.x, p1 = *(__half2*)&pv.y;                \
        float2 f0 = __half22float2(p0), f1 = __half22float2(p1);             \
        acc.x = f0.x; acc.y = f0.y; acc.z = f1.x; acc.w = f1.y;              \
    }                                                                        \
    int j  = g_rowstart[gw];                                                 \
    const int je = g_rowstart[gw + 1];                                       \
    for (; j + 4 <= je; j += 4) {                                            \
        AGG_ONE(j); AGG_ONE(j + 1); AGG_ONE(j + 2); AGG_ONE(j + 3);          \
    }                                                                        \
    for (; j < je; j++) AGG_ONE(j);                                          \
    const float dn = g_dinv[gw];                                             \
    float4 res = ((const float4*)bias)[lane];                                \
    res.x = fmaf(dn, acc.x, res.x);                                          \
    res.y = fmaf(dn, acc.y, res.y);                                          \
    res.z = fmaf(dn, acc.z, res.z);                                          \
    res.w = fmaf(dn, acc.w, res.w);

#define AGG_ONE(idx)                                                     \
    {                                                                    \
        int _s = g_csr_src[(idx)];                                       \
        uint2 _pv = hw2[(size_t)_s * 32 + lane];                         \
        __half2 _p0 = *(__half2*)&_pv.x, _p1 = *(__half2*)&_pv.y;        \
        float2 _f0 = __half22float2(_p0), _f1 = __half22float2(_p1);     \
        acc.x += _f0.x; acc.y += _f0.y; acc.z += _f1.x; acc.w += _f1.y;  \
    }

// hidden layers: relu, fp16 output
__global__ __launch_bounds__(256)
void aggregate_h_kernel(const uint2* __restrict__ hw2, const float* __restrict__ bias,
                        __half* __restrict__ out) {
    AGG_BODY();
    res.x = fmaxf(res.x, 0.f);
    res.y = fmaxf(res.y, 0.f);
    res.z = fmaxf(res.z, 0.f);
    res.w = fmaxf(res.w, 0.f);
    __half2 o0 = __floats2half2_rn(res.x, res.y);
    __half2 o1 = __floats2half2_rn(res.z, res.w);
    uint2 p;
    p.x = *(unsigned*)&o0;
    p.y = *(unsigned*)&o1;
    *(uint2*)&out[(size_t)gw * DIM + lane * 4] = p;
}

// final layer: residual, fp32 output
__global__ __launch_bounds__(256)
void aggregate_f_kernel(const uint2* __restrict__ hw2, const float* __restrict__ bias,
                        const float* __restrict__ resid, float* __restrict__ out) {
    AGG_BODY();
    float4 r = ((const float4*)resid)[(size_t)gw * 32 + lane];
    res.x += r.x; res.y += r.y; res.z += r.z; res.w += r.w;
    ((float4*)out)[(size_t)gw * 32 + lane] = res;
}
#undef AGG_ONE
#undef AGG_BODY

// ---------------- launch ----------------------------------------------------
extern "C" void kernel_launch(void* const* d_in, const int* in_sizes, int n_in,
                              void* d_out, int out_size) {
    const float* x   = (const float*)d_in[0];
    const int*   ei  = (const int*)d_in[1];
    const int*   src = ei;
    const int*   dst = ei + E_EDGES;
    const float* W0  = (const float*)d_in[2];
    const float* b0  = (const float*)d_in[3];
    const float* W1  = (const float*)d_in[4];
    const float* b1  = (const float*)d_in[5];
    const float* W2  = (const float*)d_in[6];
    const float* b2  = (const float*)d_in[7];
    float* out = (float*)d_out;

    __half *hPtr = nullptr, *hWPtr = nullptr, *WhPtr = nullptr;
    int    *degPtr = nullptr;
    cudaGetSymbolAddress((void**)&hPtr,  g_hh);
    cudaGetSymbolAddress((void**)&hWPtr, g_hWh);
    cudaGetSymbolAddress((void**)&WhPtr, g_Wh);
    cudaGetSymbolAddress((void**)&degPtr, g_deg);
    const uint2* hw2 = (const uint2*)hWPtr;

    const int smem = 2 * 128 * AS * (int)sizeof(__half);   // 69632
    static int once = 0;
    static cudaStream_t s1;
    static cudaEvent_t evFork, evDinv, evJoin;
    if (!once) {
        cudaFuncSetAttribute(hgemm128_kernel,
                             cudaFuncAttributeMaxDynamicSharedMemorySize, smem);
        cudaStreamCreateWithFlags(&s1, cudaStreamNonBlocking);
        cudaEventCreateWithFlags(&evFork, cudaEventDisableTiming);
        cudaEventCreateWithFlags(&evDinv, cudaEventDisableTiming);
        cudaEventCreateWithFlags(&evJoin, cudaEventDisableTiming);
        once = 1;
    }

    const int e4blk = (E_EDGES / 4 + 255) / 256;             // 782
    const int gblk  = (N_NODES + 127) / 128;                 // 391
    const int ablk  = (N_NODES * 32 + 255) / 256;            // 6250
    const int cblk  = (XQ + 3 * WQ + 255) / 256;             // 6298

    // ---- fork -------------------------------------------------------------
    cudaEventRecord(evFork, 0);
    cudaStreamWaitEvent(s1, evFork, 0);

    // branch A (s1): converts; GEMM0 after dinv is ready
    convert_all_kernel<<<cblk, 256, 0, s1>>>(x, W0, W1, W2);

    // branch B (main): degree + dinv
    cudaMemsetAsync(degPtr, 0, N_NODES * sizeof(int), 0);
    count_deg_kernel<<<e4blk, 256>>>(dst);
    scan_bsum_kernel<<<SCAN_NB, 256>>>();     // also writes dinv
    cudaEventRecord(evDinv, 0);

    // branch A continues: GEMM0 (needs dinv for row scaling)
    cudaStreamWaitEvent(s1, evDinv, 0);
    hgemm128_kernel<<<gblk, 256, smem, s1>>>(hPtr, WhPtr, hWPtr, N_NODES);
    cudaEventRecord(evJoin, s1);

    // branch B continues: scan + CSR fill (no dinv dependency now)
    scan_boff_kernel<<<1, 256>>>();
    scan_write_kernel<<<SCAN_NB, 256>>>();
    fill_csr_kernel<<<e4blk, 256>>>(src, dst);

    // ---- join --------------------------------------------------------------
    cudaStreamWaitEvent(0, evJoin, 0);

    // layer 0 aggregate
    aggregate_h_kernel<<<ablk, 256>>>(hw2, b0, hPtr);

    // layer 1
    hgemm128_kernel<<<gblk, 256, smem>>>(hPtr, WhPtr + DIM * DIM, hWPtr, N_NODES);
    aggregate_h_kernel<<<ablk, 256>>>(hw2, b1, hPtr);

    // layer 2: out = agg(hW) + b2 + x
    hgemm128_kernel<<<gblk, 256, smem>>>(hPtr, WhPtr + 2 * DIM * DIM, hWPtr, N_NODES);
    aggregate_f_kernel<<<ablk, 256>>>(hw2, b2, x, out);
}